// round 8
// baseline (speedup 1.0000x reference)
#include <cuda_runtime.h>
#include <cuda_bf16.h>

#define NB 16384
#define DD 2048
#define BQ 64

#define BM 128
#define BN 64
#define BK 64
#define NCHUNK (DD / BK)
#define NSTAGE 4
#define PA 68   // fp32 A stage pitch (floats); 68 % 32 == 4
#define PB 72   // bf16 pitch (elems) for Ab/Bb bufs (R1/R6-proven)

#define STAGE_BYTES (BM * PA * 4 + BN * PB * 2)  // 34816 + 9216 = 44032
#define ABUF_BYTES (BM * PB * 2)                 // 18432
#define SMEM_BYTES (NSTAGE * STAGE_BYTES + 2 * ABUF_BYTES)  // 212992

#define NCTA (NB / BM)                           // 128

__device__ __align__(16) __nv_bfloat16 g_fqB[BQ * DD];  // bf16(RN) copy of f
__device__ float g_pm[BQ * NCTA];   // [q][cta] local max (neg logits)
__device__ float g_ps[BQ * NCTA];   // [q][cta] sum exp(v - m_loc)
__device__ float g_pp[BQ * NCTA];   // [q][cta] pos min
__device__ unsigned g_cnt = 0;

#define CP_ASYNC16(dst, src)                                                  \
    asm volatile("cp.async.cg.shared.global [%0], [%1], 16;\n" ::"r"(dst),    \
                 "l"(src))
#define CP_COMMIT asm volatile("cp.async.commit_group;\n")
#define CP_WAIT(N) asm volatile("cp.async.wait_group %0;\n" ::"n"(N))

#define LDSM4(r0, r1, r2, r3, addr)                                          \
    asm volatile("ldmatrix.sync.aligned.m8n8.x4.shared.b16 {%0,%1,%2,%3}, [%4];\n" \
                 : "=r"(r0), "=r"(r1), "=r"(r2), "=r"(r3)                    \
                 : "r"(addr))

#define MMA16816(d, a, b0, b1)                                               \
    asm volatile("mma.sync.aligned.m16n8k16.row.col.f32.bf16.bf16.f32 "      \
                 "{%0,%1,%2,%3}, {%4,%5,%6,%7}, {%8,%9}, {%0,%1,%2,%3};\n"   \
                 : "+f"(d[0]), "+f"(d[1]), "+f"(d[2]), "+f"(d[3])            \
                 : "r"(a[0]), "r"(a[1]), "r"(a[2]), "r"(a[3]), "r"(b0), "r"(b1))

// ---------------------------------------------------------------------------
// K0: convert f -> bf16 (RN) once; gemm CTAs stream it via cp.async.
// ---------------------------------------------------------------------------
__global__ __launch_bounds__(256) void prep_kernel(const float* __restrict__ fq)
{
    int t = blockIdx.x * 256 + threadIdx.x;  // 128 blocks -> 32768 float4s
    float4 v = ((const float4*)fq)[t];
    __nv_bfloat162 p0 = __floats2bfloat162_rn(v.x, v.y);
    __nv_bfloat162 p1 = __floats2bfloat162_rn(v.z, v.w);
    uint2 u;
    u.x = *(unsigned*)&p0;
    u.y = *(unsigned*)&p1;
    ((uint2*)g_fqB)[t] = u;
}

// ---------------------------------------------------------------------------
// K1: the whole problem minus prep.
//  - bf16 mma via ldmatrix; convert-ahead single-barrier cp.async pipeline
//  - dense lane-contiguous streamed copy features -> out+1 (scalar STG.32:
//    out+1 is only 4-byte aligned)
//  - epilogue: per-CTA loss partials; LAST CTA (counter) combines 128 partials
//    in fixed order -> mean loss -> out[0]; counter reset for graph replay
//  - momentum update done by the CTA owning the bank rows
// ---------------------------------------------------------------------------
__global__ __launch_bounds__(256) void gemm_kernel(
    const float* __restrict__ feats,   // [16384, 2048]
    const int* __restrict__ labels,    // [16384]
    const int* __restrict__ indexes,   // [64]
    const float* __restrict__ fweak,   // [64, 2048]
    float* __restrict__ out)           // [0]=loss, [1:]=updated_features
{
    extern __shared__ __align__(16) char smem[];
    __shared__ int slab[BM];
    __shared__ int sblab[BQ];
    __shared__ float sMx[256], sPn[256], sSm[256];
    __shared__ int s_last;

    float* const outF = out + 1;

    const int tid  = threadIdx.x;
    const int lane = tid & 31;
    const int warp = tid >> 5;
    const int wm = warp & 3;   // 4 warps along M (j)
    const int wn = warp >> 2;  // 2 warps along N (b)
    const int rowBase = blockIdx.x * BM;

    const int c4 = tid & 15;   // float4 col within 64-col chunk
    const int r0 = tid >> 4;   // base row (step 16)

    if (tid < BM) slab[tid] = labels[rowBase + tid];
    if (tid < BQ) sblab[tid] = labels[indexes[tid]];

    float acc[2][4][4];
#pragma unroll
    for (int i = 0; i < 2; i++)
#pragma unroll
        for (int j = 0; j < 4; j++)
#pragma unroll
            for (int k = 0; k < 4; k++) acc[i][j][k] = 0.f;

    auto stA  = [&](int s) { return (float*)(smem + s * STAGE_BYTES); };
    auto stB  = [&](int s) {
        return (__nv_bfloat16*)(smem + s * STAGE_BYTES + BM * PA * 4);
    };
    auto bufA = [&](int d) {
        return (__nv_bfloat16*)(smem + NSTAGE * STAGE_BYTES + d * ABUF_BYTES);
    };

    auto prefetch = [&](int ck) {
        const int s = ck & (NSTAGE - 1);
        float* A = stA(s);
        const float* src = feats + (size_t)rowBase * DD + ck * BK;
#pragma unroll
        for (int j = 0; j < 8; j++) {
            int r = r0 + 16 * j;
            unsigned d =
                (unsigned)__cvta_generic_to_shared(A + r * PA + c4 * 4);
            CP_ASYNC16(d, src + (size_t)r * DD + c4 * 4);
        }
        __nv_bfloat16* B = stB(s);
        const __nv_bfloat16* bsrc = g_fqB + ck * BK;
        {
            int row = tid >> 2;
            int p = tid & 3;
            unsigned d0 =
                (unsigned)__cvta_generic_to_shared(B + row * PB + p * 8);
            CP_ASYNC16(d0, bsrc + (size_t)row * DD + p * 8);
            unsigned d1 =
                (unsigned)__cvta_generic_to_shared(B + row * PB + (p + 4) * 8);
            CP_ASYNC16(d1, bsrc + (size_t)row * DD + (p + 4) * 8);
        }
        CP_COMMIT;
    };

    // convert chunk ck: bf16 pack into Ab + dense streamed copy to outF
    auto convert = [&](int ck) {
        const float* A = stA(ck & (NSTAGE - 1));
        __nv_bfloat16* Ab = bufA(ck & 1);
#pragma unroll
        for (int j = 0; j < 8; j++) {
            int r = r0 + 16 * j;
            float4 v = *(const float4*)(A + r * PA + c4 * 4);
            __nv_bfloat162 h0 = __floats2bfloat162_rn(v.x, v.y);
            __nv_bfloat162 h1 = __floats2bfloat162_rn(v.z, v.w);
            uint2 u;
            u.x = *(unsigned*)&h0;
            u.y = *(unsigned*)&h1;
            *(uint2*)(Ab + r * PB + c4 * 4) = u;
        }
        // dense copy: lanes contiguous -> 1 wavefront per STG.32
        float* orow = outF + (size_t)rowBase * DD + ck * BK;
#pragma unroll
        for (int j = 0; j < 16; j++) {
            int r = warp + 8 * j;
            __stcs(orow + (size_t)r * DD + lane,      A[r * PA + lane]);
            __stcs(orow + (size_t)r * DD + 32 + lane, A[r * PA + 32 + lane]);
        }
    };

    const int matid = lane >> 3, mr = lane & 7;

    // prologue
    prefetch(0);
    prefetch(1);
    prefetch(2);
    CP_WAIT(2);          // group 0 complete (this thread)
    __syncthreads();     // ... and all threads
    convert(0);

#pragma unroll 1
    for (int c = 0; c < NCHUNK; c++) {
        if (c + 1 < NCHUNK) {
            if (c + 2 <= NCHUNK - 1) CP_WAIT(1);
            else                     CP_WAIT(0);
        }
        __syncthreads();
        if (c + 3 < NCHUNK) prefetch(c + 3);
        if (c + 1 < NCHUNK) convert(c + 1);

        const __nv_bfloat16* Ab = bufA(c & 1);
        const __nv_bfloat16* Bs = stB(c & (NSTAGE - 1));
#pragma unroll
        for (int ks = 0; ks < 4; ks++) {
            unsigned af[2][4], bf2[2][4];
#pragma unroll
            for (int mi = 0; mi < 2; mi++) {
                const __nv_bfloat16* p =
                    Ab + (wm * 32 + mi * 16 + (matid & 1) * 8 + mr) * PB +
                    ks * 16 + (matid >> 1) * 8;
                unsigned ad = (unsigned)__cvta_generic_to_shared(p);
                LDSM4(af[mi][0], af[mi][1], af[mi][2], af[mi][3], ad);
            }
#pragma unroll
            for (int gi = 0; gi < 2; gi++) {
                const __nv_bfloat16* p =
                    Bs + (wn * 32 + gi * 16 + (matid >> 1) * 8 + mr) * PB +
                    ks * 16 + (matid & 1) * 8;
                unsigned ad = (unsigned)__cvta_generic_to_shared(p);
                LDSM4(bf2[gi][0], bf2[gi][1], bf2[gi][2], bf2[gi][3], ad);
            }
#pragma unroll
            for (int mi = 0; mi < 2; mi++)
#pragma unroll
                for (int nt = 0; nt < 4; nt++)
                    MMA16816(acc[mi][nt], af[mi],
                             bf2[nt >> 1][(nt & 1) * 2],
                             bf2[nt >> 1][(nt & 1) * 2 + 1]);
        }
    }

    // ---- epilogue: accums -> smem sC[j][b] ----
    __syncthreads();
    float* sC = (float*)smem;  // [128][65]
    const int g = lane >> 2, t4 = lane & 3;
#pragma unroll
    for (int mi = 0; mi < 2; mi++)
#pragma unroll
        for (int nt = 0; nt < 4; nt++) {
            int ml = wm * 32 + mi * 16 + g;
            int nn = wn * 32 + nt * 8 + t4 * 2;
            sC[ml * 65 + nn]           = acc[mi][nt][0];
            sC[ml * 65 + nn + 1]       = acc[mi][nt][1];
            sC[(ml + 8) * 65 + nn]     = acc[mi][nt][2];
            sC[(ml + 8) * 65 + nn + 1] = acc[mi][nt][3];
        }
    __syncthreads();

    // per-CTA loss partials: 4 threads per query, 32 rows each
    const float it = 1.0f / 0.07f;
    const int q = tid & 63, kk = tid >> 6;
    const int blab = sblab[q];
    float mneg = -INFINITY, pmin = INFINITY;
#pragma unroll 4
    for (int j = kk * 32; j < kk * 32 + 32; j++) {
        float v = sC[j * 65 + q] * it;
        if (slab[j] != blab) mneg = fmaxf(mneg, v);
        else                 pmin = fminf(pmin, v);
    }
    sMx[tid] = mneg; sPn[tid] = pmin;
    __syncthreads();
    if (tid < 64) {
        float m = fmaxf(fmaxf(sMx[tid], sMx[tid + 64]),
                        fmaxf(sMx[tid + 128], sMx[tid + 192]));
        float p = fminf(fminf(sPn[tid], sPn[tid + 64]),
                        fminf(sPn[tid + 128], sPn[tid + 192]));
        sMx[tid] = m;  // m_cta for query tid
        sPn[tid] = p;
    }
    __syncthreads();
    const float mC = sMx[q];
    const float thr = mC - 25.0f;   // exp(-25)~1.4e-11: exact vs top-K lse
    float s = 0.f;
    if (mneg > thr) {
#pragma unroll 4
        for (int j = kk * 32; j < kk * 32 + 32; j++) {
            float v = sC[j * 65 + q] * it;
            if (slab[j] != blab && v > thr) s += __expf(v - mC);
        }
    }
    sSm[tid] = s;
    __syncthreads();
    if (tid < 64) {
        float sc = sSm[tid] + sSm[tid + 64] + sSm[tid + 128] + sSm[tid + 192];
        int o = tid * NCTA + blockIdx.x;   // [q][cta] -> coalesced combine
        g_pm[o] = sMx[tid];
        g_ps[o] = sc;
        g_pp[o] = sPn[tid];
    }
    __syncthreads();
    if (tid == 0) {
        __threadfence();
        unsigned c = atomicAdd(&g_cnt, 1u);
        s_last = (c == NCTA - 1);
    }
    __syncthreads();

    // ---- last CTA: combine 128 partials per query, mean -> out[0] ----
    if (s_last) {
        // pass 1: M, P per query (4 threads/query, 32 ctas each)
        float m_p = -INFINITY, p_p = INFINITY;
#pragma unroll 4
        for (int i = kk * 32; i < kk * 32 + 32; i++) {
            m_p = fmaxf(m_p, *((volatile float*)&g_pm[q * NCTA + i]));
            p_p = fminf(p_p, *((volatile float*)&g_pp[q * NCTA + i]));
        }
        sMx[tid] = m_p; sPn[tid] = p_p;
        __syncthreads();
        if (tid < 64) {
            sMx[tid] = fmaxf(fmaxf(sMx[tid], sMx[tid + 64]),
                             fmaxf(sMx[tid + 128], sMx[tid + 192]));
            sPn[tid] = fminf(fminf(sPn[tid], sPn[tid + 64]),
                             fminf(sPn[tid + 128], sPn[tid + 192]));
        }
        __syncthreads();
        const float M = sMx[q];
        // pass 2: S = sum s_i * exp(m_i - M), fixed index order
        float s_p = 0.f;
#pragma unroll 4
        for (int i = kk * 32; i < kk * 32 + 32; i++) {
            float mi = *((volatile float*)&g_pm[q * NCTA + i]);
            if (mi > -INFINITY)
                s_p += *((volatile float*)&g_ps[q * NCTA + i]) *
                       __expf(mi - M);
        }
        sSm[tid] = s_p;
        __syncthreads();
        if (tid < 64) {
            float S = sSm[tid] + sSm[tid + 64] + sSm[tid + 128] +
                      sSm[tid + 192];
            float P = sPn[tid];
            float Mq = sMx[tid];
            float nm = fmaxf(Mq, P);
            float ns = S * __expf(Mq - nm) + __expf(P - nm);
            sSm[tid] = nm + logf(ns) - P;  // lse - logit0 for query tid
        } else {
            sSm[tid] = 0.f;
        }
        __syncthreads();
        for (int o = 32; o > 0; o >>= 1) {
            if (tid < o) sSm[tid] += sSm[tid + o];
            __syncthreads();
        }
        if (tid == 0) {
            out[0] = sSm[0] * (1.0f / 64.0f);
            g_cnt = 0;  // reset for next graph replay
        }
    }
    __syncthreads();

    // ---- momentum update: this CTA owns rows [rowBase, rowBase+128) ----
#pragma unroll 1
    for (int b = 0; b < BQ; b++) {
        int idx = indexes[b];
        if (idx < rowBase || idx >= rowBase + BM) continue;
        bool own = true;
        for (int b2 = b + 1; b2 < BQ; b2++)
            if (indexes[b2] == idx) own = false;   // last duplicate wins
        if (!own) continue;

        float w[8];
        float ssum = 0.f;
        const float* fr = feats + (size_t)idx * DD;
        const float* wr = fweak + (size_t)b * DD;
#pragma unroll
        for (int i = 0; i < 8; i++) {
            int k = i * 256 + tid;
            float v = fr[k] * 0.2f + wr[k] * 0.8f;
            w[i] = v;
            ssum += v * v;
        }
        sMx[tid] = ssum;
        __syncthreads();
        for (int o = 128; o > 0; o >>= 1) {
            if (tid < o) sMx[tid] += sMx[tid + o];
            __syncthreads();
        }
        float inv = 1.0f / fmaxf(sqrtf(sMx[0]), 1e-12f);
        float* orow = outF + (size_t)idx * DD;
#pragma unroll
        for (int i = 0; i < 8; i++) orow[i * 256 + tid] = w[i] * inv;
        __syncthreads();
    }
}

// ---------------------------------------------------------------------------
extern "C" void kernel_launch(void* const* d_in, const int* in_sizes, int n_in,
                              void* d_out, int out_size)
{
    const float* fq      = (const float*)d_in[0];  // f        [64,2048]
    const float* fweak   = (const float*)d_in[1];  // f_weak   [64,2048]
    const int*   indexes = (const int*)d_in[2];    // [64]
    const float* feats   = (const float*)d_in[3];  // features [16384,2048]
    const int*   labels  = (const int*)d_in[4];    // [16384]
    float* out = (float*)d_out;                    // [0]=loss, [1:]=features

    cudaFuncSetAttribute(gemm_kernel,
                         cudaFuncAttributeMaxDynamicSharedMemorySize,
                         SMEM_BYTES);

    prep_kernel<<<BQ * DD / (256 * 4), 256>>>(fq);
    gemm_kernel<<<NCTA, 256, SMEM_BYTES>>>(feats, labels, indexes, fweak, out);
}

// round 9
// speedup vs baseline: 1.3735x; 1.3735x over previous
#include <cuda_runtime.h>
#include <cuda_bf16.h>

#define NB 16384
#define DD 2048
#define BQ 64

#define BM 128
#define BN 64
#define BK 64
#define NCHUNK (DD / BK)
#define NSTAGE 4
#define PA 68   // fp32 A stage pitch (floats); 68 % 32 == 4
#define PB 72   // bf16 pitch (elems) for Ab/Bb bufs (R1/R6-proven)

#define STAGE_BYTES (BM * PA * 4 + BN * PB * 2)  // 34816 + 9216 = 44032
#define ABUF_BYTES (BM * PB * 2)                 // 18432
#define SMEM_BYTES (NSTAGE * STAGE_BYTES + 2 * ABUF_BYTES)  // 212992

#define NCTA (NB / BM)                           // 128

__device__ __align__(16) __nv_bfloat16 g_fqB[BQ * DD];  // bf16(RN) copy of f
__device__ float g_pm[BQ * NCTA];   // [q][cta] local max (neg logits)
__device__ float g_ps[BQ * NCTA];   // [q][cta] sum exp(v - m_loc)
__device__ float g_pp[BQ * NCTA];   // [q][cta] pos min
__device__ unsigned g_cnt = 0;

#define CP_ASYNC16(dst, src)                                                  \
    asm volatile("cp.async.cg.shared.global [%0], [%1], 16;\n" ::"r"(dst),    \
                 "l"(src))
#define CP_COMMIT asm volatile("cp.async.commit_group;\n")
#define CP_WAIT(N) asm volatile("cp.async.wait_group %0;\n" ::"n"(N))

#define LDSM4(r0, r1, r2, r3, addr)                                          \
    asm volatile("ldmatrix.sync.aligned.m8n8.x4.shared.b16 {%0,%1,%2,%3}, [%4];\n" \
                 : "=r"(r0), "=r"(r1), "=r"(r2), "=r"(r3)                    \
                 : "r"(addr))

#define MMA16816(d, a, b0, b1)                                               \
    asm volatile("mma.sync.aligned.m16n8k16.row.col.f32.bf16.bf16.f32 "      \
                 "{%0,%1,%2,%3}, {%4,%5,%6,%7}, {%8,%9}, {%0,%1,%2,%3};\n"   \
                 : "+f"(d[0]), "+f"(d[1]), "+f"(d[2]), "+f"(d[3])            \
                 : "r"(a[0]), "r"(a[1]), "r"(a[2]), "r"(a[3]), "r"(b0), "r"(b1))

// ---------------------------------------------------------------------------
// K0: convert f -> bf16 (RN) once; gemm CTAs stream it via cp.async.
// ---------------------------------------------------------------------------
__global__ __launch_bounds__(256) void prep_kernel(const float* __restrict__ fq)
{
    int t = blockIdx.x * 256 + threadIdx.x;  // 128 blocks -> 32768 float4s
    float4 v = ((const float4*)fq)[t];
    __nv_bfloat162 p0 = __floats2bfloat162_rn(v.x, v.y);
    __nv_bfloat162 p1 = __floats2bfloat162_rn(v.z, v.w);
    uint2 u;
    u.x = *(unsigned*)&p0;
    u.y = *(unsigned*)&p1;
    ((uint2*)g_fqB)[t] = u;
}

// ---------------------------------------------------------------------------
// K1: the whole problem minus prep.
//  - bf16 mma via ldmatrix; convert-ahead single-barrier cp.async pipeline
//  - fused streamed copy features -> out+1 reusing the conversion loads
//    (scalar STG.32: out+1 is only 4-byte aligned)
//  - epilogue: per-CTA loss partials; LAST CTA (counter) combines 128
//    partials in fixed order -> mean loss -> out[0]; counter reset for replay
//  - momentum update done by the CTA owning the bank rows
//  - launch_bounds(256, 1): 1 CTA/SM (smem-forced anyway) so ptxas does NOT
//    cap at 64 regs and spill the accumulators (the R8 regression).
// ---------------------------------------------------------------------------
__global__ __launch_bounds__(256, 1) void gemm_kernel(
    const float* __restrict__ feats,   // [16384, 2048]
    const int* __restrict__ labels,    // [16384]
    const int* __restrict__ indexes,   // [64]
    const float* __restrict__ fweak,   // [64, 2048]
    float* __restrict__ out)           // [0]=loss, [1:]=updated_features
{
    extern __shared__ __align__(16) char smem[];
    __shared__ int slab[BM];
    __shared__ int sblab[BQ];
    __shared__ float sMx[256], sPn[256], sSm[256];
    __shared__ int s_last;

    float* const outF = out + 1;

    const int tid  = threadIdx.x;
    const int lane = tid & 31;
    const int warp = tid >> 5;
    const int wm = warp & 3;   // 4 warps along M (j)
    const int wn = warp >> 2;  // 2 warps along N (b)
    const int rowBase = blockIdx.x * BM;

    const int c4 = tid & 15;   // float4 col within 64-col chunk
    const int r0 = tid >> 4;   // base row (step 16)

    if (tid < BM) slab[tid] = labels[rowBase + tid];
    if (tid < BQ) sblab[tid] = labels[indexes[tid]];

    float acc[2][4][4];
#pragma unroll
    for (int i = 0; i < 2; i++)
#pragma unroll
        for (int j = 0; j < 4; j++)
#pragma unroll
            for (int k = 0; k < 4; k++) acc[i][j][k] = 0.f;

    auto stA  = [&](int s) { return (float*)(smem + s * STAGE_BYTES); };
    auto stB  = [&](int s) {
        return (__nv_bfloat16*)(smem + s * STAGE_BYTES + BM * PA * 4);
    };
    auto bufA = [&](int d) {
        return (__nv_bfloat16*)(smem + NSTAGE * STAGE_BYTES + d * ABUF_BYTES);
    };

    auto prefetch = [&](int ck) {
        const int s = ck & (NSTAGE - 1);
        float* A = stA(s);
        const float* src = feats + (size_t)rowBase * DD + ck * BK;
#pragma unroll
        for (int j = 0; j < 8; j++) {
            int r = r0 + 16 * j;
            unsigned d =
                (unsigned)__cvta_generic_to_shared(A + r * PA + c4 * 4);
            CP_ASYNC16(d, src + (size_t)r * DD + c4 * 4);
        }
        __nv_bfloat16* B = stB(s);
        const __nv_bfloat16* bsrc = g_fqB + ck * BK;
        {
            int row = tid >> 2;
            int p = tid & 3;
            unsigned d0 =
                (unsigned)__cvta_generic_to_shared(B + row * PB + p * 8);
            CP_ASYNC16(d0, bsrc + (size_t)row * DD + p * 8);
            unsigned d1 =
                (unsigned)__cvta_generic_to_shared(B + row * PB + (p + 4) * 8);
            CP_ASYNC16(d1, bsrc + (size_t)row * DD + (p + 4) * 8);
        }
        CP_COMMIT;
    };

    // convert chunk ck: fp32 stage -> streamed copy to outF + bf16 Ab buffer
    auto convert = [&](int ck) {
        const float* A = stA(ck & (NSTAGE - 1));
        __nv_bfloat16* Ab = bufA(ck & 1);
        float* orow = outF + (size_t)rowBase * DD + ck * BK;
#pragma unroll
        for (int j = 0; j < 8; j++) {
            int r = r0 + 16 * j;
            float4 v = *(const float4*)(A + r * PA + c4 * 4);
            float* p = orow + (size_t)r * DD + c4 * 4;
            __stcs(p + 0, v.x);
            __stcs(p + 1, v.y);
            __stcs(p + 2, v.z);
            __stcs(p + 3, v.w);
            __nv_bfloat162 h0 = __floats2bfloat162_rn(v.x, v.y);
            __nv_bfloat162 h1 = __floats2bfloat162_rn(v.z, v.w);
            uint2 u;
            u.x = *(unsigned*)&h0;
            u.y = *(unsigned*)&h1;
            *(uint2*)(Ab + r * PB + c4 * 4) = u;
        }
    };

    const int matid = lane >> 3, mr = lane & 7;

    // prologue
    prefetch(0);
    prefetch(1);
    prefetch(2);
    CP_WAIT(2);          // group 0 complete (this thread)
    __syncthreads();     // ... and all threads
    convert(0);

#pragma unroll 1
    for (int c = 0; c < NCHUNK; c++) {
        if (c + 1 < NCHUNK) {
            if (c + 2 <= NCHUNK - 1) CP_WAIT(1);
            else                     CP_WAIT(0);
        }
        __syncthreads();
        if (c + 3 < NCHUNK) prefetch(c + 3);
        if (c + 1 < NCHUNK) convert(c + 1);

        const __nv_bfloat16* Ab = bufA(c & 1);
        const __nv_bfloat16* Bs = stB(c & (NSTAGE - 1));
#pragma unroll
        for (int ks = 0; ks < 4; ks++) {
            unsigned af[2][4], bf2[2][4];
#pragma unroll
            for (int mi = 0; mi < 2; mi++) {
                const __nv_bfloat16* p =
                    Ab + (wm * 32 + mi * 16 + (matid & 1) * 8 + mr) * PB +
                    ks * 16 + (matid >> 1) * 8;
                unsigned ad = (unsigned)__cvta_generic_to_shared(p);
                LDSM4(af[mi][0], af[mi][1], af[mi][2], af[mi][3], ad);
            }
#pragma unroll
            for (int gi = 0; gi < 2; gi++) {
                const __nv_bfloat16* p =
                    Bs + (wn * 32 + gi * 16 + (matid >> 1) * 8 + mr) * PB +
                    ks * 16 + (matid & 1) * 8;
                unsigned ad = (unsigned)__cvta_generic_to_shared(p);
                LDSM4(bf2[gi][0], bf2[gi][1], bf2[gi][2], bf2[gi][3], ad);
            }
#pragma unroll
            for (int mi = 0; mi < 2; mi++)
#pragma unroll
                for (int nt = 0; nt < 4; nt++)
                    MMA16816(acc[mi][nt], af[mi],
                             bf2[nt >> 1][(nt & 1) * 2],
                             bf2[nt >> 1][(nt & 1) * 2 + 1]);
        }
    }

    // ---- epilogue: accums -> smem sC[j][b] ----
    __syncthreads();
    float* sC = (float*)smem;  // [128][65]
    const int g = lane >> 2, t4 = lane & 3;
#pragma unroll
    for (int mi = 0; mi < 2; mi++)
#pragma unroll
        for (int nt = 0; nt < 4; nt++) {
            int ml = wm * 32 + mi * 16 + g;
            int nn = wn * 32 + nt * 8 + t4 * 2;
            sC[ml * 65 + nn]           = acc[mi][nt][0];
            sC[ml * 65 + nn + 1]       = acc[mi][nt][1];
            sC[(ml + 8) * 65 + nn]     = acc[mi][nt][2];
            sC[(ml + 8) * 65 + nn + 1] = acc[mi][nt][3];
        }
    __syncthreads();

    // per-CTA loss partials: 4 threads per query, 32 rows each
    const float it = 1.0f / 0.07f;
    const int q = tid & 63, kk = tid >> 6;
    const int blab = sblab[q];
    float mneg = -INFINITY, pmin = INFINITY;
#pragma unroll 4
    for (int j = kk * 32; j < kk * 32 + 32; j++) {
        float v = sC[j * 65 + q] * it;
        if (slab[j] != blab) mneg = fmaxf(mneg, v);
        else                 pmin = fminf(pmin, v);
    }
    sMx[tid] = mneg; sPn[tid] = pmin;
    __syncthreads();
    if (tid < 64) {
        float m = fmaxf(fmaxf(sMx[tid], sMx[tid + 64]),
                        fmaxf(sMx[tid + 128], sMx[tid + 192]));
        float p = fminf(fminf(sPn[tid], sPn[tid + 64]),
                        fminf(sPn[tid + 128], sPn[tid + 192]));
        sMx[tid] = m;  // m_cta for query tid
        sPn[tid] = p;
    }
    __syncthreads();
    const float mC = sMx[q];
    const float thr = mC - 25.0f;   // exp(-25)~1.4e-11: exact vs top-K lse
    float s = 0.f;
    if (mneg > thr) {
#pragma unroll 4
        for (int j = kk * 32; j < kk * 32 + 32; j++) {
            float v = sC[j * 65 + q] * it;
            if (slab[j] != blab && v > thr) s += __expf(v - mC);
        }
    }
    sSm[tid] = s;
    __syncthreads();
    if (tid < 64) {
        float sc = sSm[tid] + sSm[tid + 64] + sSm[tid + 128] + sSm[tid + 192];
        int o = tid * NCTA + blockIdx.x;   // [q][cta] -> coalesced combine
        g_pm[o] = sMx[tid];
        g_ps[o] = sc;
        g_pp[o] = sPn[tid];
    }
    __syncthreads();
    if (tid == 0) {
        __threadfence();
        unsigned c = atomicAdd(&g_cnt, 1u);
        s_last = (c == NCTA - 1);
    }
    __syncthreads();

    // ---- last CTA: combine 128 partials per query, mean -> out[0] ----
    if (s_last) {
        // pass 1: M, P per query (4 threads/query, 32 ctas each)
        float m_p = -INFINITY, p_p = INFINITY;
#pragma unroll 4
        for (int i = kk * 32; i < kk * 32 + 32; i++) {
            m_p = fmaxf(m_p, *((volatile float*)&g_pm[q * NCTA + i]));
            p_p = fminf(p_p, *((volatile float*)&g_pp[q * NCTA + i]));
        }
        sMx[tid] = m_p; sPn[tid] = p_p;
        __syncthreads();
        if (tid < 64) {
            sMx[tid] = fmaxf(fmaxf(sMx[tid], sMx[tid + 64]),
                             fmaxf(sMx[tid + 128], sMx[tid + 192]));
            sPn[tid] = fminf(fminf(sPn[tid], sPn[tid + 64]),
                             fminf(sPn[tid + 128], sPn[tid + 192]));
        }
        __syncthreads();
        const float M = sMx[q];
        // pass 2: S = sum s_i * exp(m_i - M), fixed index order
        float s_p = 0.f;
#pragma unroll 4
        for (int i = kk * 32; i < kk * 32 + 32; i++) {
            float mi = *((volatile float*)&g_pm[q * NCTA + i]);
            if (mi > -INFINITY)
                s_p += *((volatile float*)&g_ps[q * NCTA + i]) *
                       __expf(mi - M);
        }
        sSm[tid] = s_p;
        __syncthreads();
        if (tid < 64) {
            float S = sSm[tid] + sSm[tid + 64] + sSm[tid + 128] +
                      sSm[tid + 192];
            float P = sPn[tid];
            float Mq = sMx[tid];
            float nm = fmaxf(Mq, P);
            float ns = S * __expf(Mq - nm) + __expf(P - nm);
            sSm[tid] = nm + logf(ns) - P;  // lse - logit0 for query tid
        } else {
            sSm[tid] = 0.f;
        }
        __syncthreads();
        for (int o = 32; o > 0; o >>= 1) {
            if (tid < o) sSm[tid] += sSm[tid + o];
            __syncthreads();
        }
        if (tid == 0) {
            out[0] = sSm[0] * (1.0f / 64.0f);
            g_cnt = 0;  // reset for next graph replay
        }
    }
    __syncthreads();

    // ---- momentum update: this CTA owns rows [rowBase, rowBase+128) ----
#pragma unroll 1
    for (int b = 0; b < BQ; b++) {
        int idx = indexes[b];
        if (idx < rowBase || idx >= rowBase + BM) continue;
        bool own = true;
        for (int b2 = b + 1; b2 < BQ; b2++)
            if (indexes[b2] == idx) own = false;   // last duplicate wins
        if (!own) continue;

        float w[8];
        float ssum = 0.f;
        const float* fr = feats + (size_t)idx * DD;
        const float* wr = fweak + (size_t)b * DD;
#pragma unroll
        for (int i = 0; i < 8; i++) {
            int k = i * 256 + tid;
            float v = fr[k] * 0.2f + wr[k] * 0.8f;
            w[i] = v;
            ssum += v * v;
        }
        sMx[tid] = ssum;
        __syncthreads();
        for (int o = 128; o > 0; o >>= 1) {
            if (tid < o) sMx[tid] += sMx[tid + o];
            __syncthreads();
        }
        float inv = 1.0f / fmaxf(sqrtf(sMx[0]), 1e-12f);
        float* orow = outF + (size_t)idx * DD;
#pragma unroll
        for (int i = 0; i < 8; i++) orow[i * 256 + tid] = w[i] * inv;
        __syncthreads();
    }
}

// ---------------------------------------------------------------------------
extern "C" void kernel_launch(void* const* d_in, const int* in_sizes, int n_in,
                              void* d_out, int out_size)
{
    const float* fq      = (const float*)d_in[0];  // f        [64,2048]
    const float* fweak   = (const float*)d_in[1];  // f_weak   [64,2048]
    const int*   indexes = (const int*)d_in[2];    // [64]
    const float* feats   = (const float*)d_in[3];  // features [16384,2048]
    const int*   labels  = (const int*)d_in[4];    // [16384]
    float* out = (float*)d_out;                    // [0]=loss, [1:]=features

    cudaFuncSetAttribute(gemm_kernel,
                         cudaFuncAttributeMaxDynamicSharedMemorySize,
                         SMEM_BYTES);

    prep_kernel<<<BQ * DD / (256 * 4), 256>>>(fq);
    gemm_kernel<<<NCTA, 256, SMEM_BYTES>>>(feats, labels, indexes, fweak, out);
}

// round 10
// speedup vs baseline: 2.1084x; 1.5350x over previous
#include <cuda_runtime.h>
#include <cuda_bf16.h>

#define NB 16384
#define DD 2048
#define BQ 64

#define BM 128
#define BN 64
#define BK 64
#define NCHUNK (DD / BK)
#define NSTAGE 4
#define PA 68   // fp32 A stage pitch (floats); 68 % 32 == 4
#define PB 72   // bf16 pitch (elems) for B stages and A bufs (R1/R6-proven)

#define STAGE_BYTES (BM * PA * 4 + BN * PB * 2)  // 34816 + 9216 = 44032
#define ABUF_BYTES (BM * PB * 2)                 // 18432
#define SMEM_BYTES (NSTAGE * STAGE_BYTES + 2 * ABUF_BYTES)  // 212992

__device__ float g_mat[BQ * NB];
__device__ __align__(16) __nv_bfloat16 g_fqB[BQ * DD];  // bf16(RN) copy of f
__device__ float g_qm[BQ * 4], g_qs[BQ * 4], g_qp[BQ * 4];
__device__ unsigned g_cnt = 0;

#define CP_ASYNC16(dst, src)                                                  \
    asm volatile("cp.async.cg.shared.global [%0], [%1], 16;\n" ::"r"(dst),    \
                 "l"(src))
#define CP_COMMIT asm volatile("cp.async.commit_group;\n")
#define CP_WAIT(N) asm volatile("cp.async.wait_group %0;\n" ::"n"(N))

#define LDSM4(r0, r1, r2, r3, addr)                                          \
    asm volatile("ldmatrix.sync.aligned.m8n8.x4.shared.b16 {%0,%1,%2,%3}, [%4];\n" \
                 : "=r"(r0), "=r"(r1), "=r"(r2), "=r"(r3)                    \
                 : "r"(addr))

#define MMA16816(d, a, b0, b1)                                               \
    asm volatile("mma.sync.aligned.m16n8k16.row.col.f32.bf16.bf16.f32 "      \
                 "{%0,%1,%2,%3}, {%4,%5,%6,%7}, {%8,%9}, {%0,%1,%2,%3};\n"   \
                 : "+f"(d[0]), "+f"(d[1]), "+f"(d[2]), "+f"(d[3])            \
                 : "r"(a[0]), "r"(a[1]), "r"(a[2]), "r"(a[3]), "r"(b0), "r"(b1))

// ---------------------------------------------------------------------------
// K0: convert f -> bf16 (RN) once; all gemm CTAs reuse it (L2-resident).
// ---------------------------------------------------------------------------
__global__ __launch_bounds__(256) void prep_kernel(const float* __restrict__ fq)
{
    int t = blockIdx.x * 256 + threadIdx.x;  // 128 blocks -> 32768 float4s
    float4 v = ((const float4*)fq)[t];
    __nv_bfloat162 p0 = __floats2bfloat162_rn(v.x, v.y);
    __nv_bfloat162 p1 = __floats2bfloat162_rn(v.z, v.w);
    uint2 u;
    u.x = *(unsigned*)&p0;
    u.y = *(unsigned*)&p1;
    ((uint2*)g_fqB)[t] = u;
}

// ---------------------------------------------------------------------------
// K1: mat[j,b] = features[j,:] . f[b,:]  (bf16 mma via ldmatrix, fp32 accum)
// Convert-ahead pipeline: ONE barrier per chunk; convert/copy of chunk c+1
// overlaps (instruction-interleaved) with mma of chunk c.
// Copy-out is DENSE (lane-contiguous -> 1 L1 wavefront per STG.32) — the one
// change vs the proven R6 kernel. outF = d_out+1 is 4-byte aligned -> STG.32.
// ---------------------------------------------------------------------------
__global__ __launch_bounds__(256) void gemm_copy_kernel(
    const float* __restrict__ feats,   // [16384, 2048]
    float* __restrict__ outF)          // d_out + 1 (misaligned for float4!)
{
    extern __shared__ __align__(16) char smem[];

    const int tid  = threadIdx.x;
    const int lane = tid & 31;
    const int warp = tid >> 5;
    const int wm = warp & 3;   // 4 warps along M (j)
    const int wn = warp >> 2;  // 2 warps along N (b)
    const int rowBase = blockIdx.x * BM;

    const int c4 = tid & 15;   // float4 col within 64-col chunk
    const int r0 = tid >> 4;   // base row (step 16)

    float acc[2][4][4];
#pragma unroll
    for (int i = 0; i < 2; i++)
#pragma unroll
        for (int j = 0; j < 4; j++)
#pragma unroll
            for (int k = 0; k < 4; k++) acc[i][j][k] = 0.f;

    auto stA  = [&](int s) { return (float*)(smem + s * STAGE_BYTES); };
    auto stB  = [&](int s) {
        return (__nv_bfloat16*)(smem + s * STAGE_BYTES + BM * PA * 4);
    };
    auto bufA = [&](int d) {
        return (__nv_bfloat16*)(smem + NSTAGE * STAGE_BYTES + d * ABUF_BYTES);
    };

    auto prefetch = [&](int ck) {
        const int s = ck & (NSTAGE - 1);
        float* A = stA(s);
        const float* src = feats + (size_t)rowBase * DD + ck * BK;
#pragma unroll
        for (int j = 0; j < 8; j++) {
            int r = r0 + 16 * j;
            unsigned d =
                (unsigned)__cvta_generic_to_shared(A + r * PA + c4 * 4);
            CP_ASYNC16(d, src + (size_t)r * DD + c4 * 4);
        }
        __nv_bfloat16* B = stB(s);
        const __nv_bfloat16* bsrc = g_fqB + ck * BK;
        {
            int row = tid >> 2;
            int p = tid & 3;
            unsigned d0 =
                (unsigned)__cvta_generic_to_shared(B + row * PB + p * 8);
            CP_ASYNC16(d0, bsrc + (size_t)row * DD + p * 8);
            unsigned d1 =
                (unsigned)__cvta_generic_to_shared(B + row * PB + (p + 4) * 8);
            CP_ASYNC16(d1, bsrc + (size_t)row * DD + (p + 4) * 8);
        }
        CP_COMMIT;
    };

    // convert chunk ck: bf16 pack into Ab (float4 path) + DENSE copy to outF
    auto convert = [&](int ck) {
        const float* A = stA(ck & (NSTAGE - 1));
        __nv_bfloat16* Ab = bufA(ck & 1);
#pragma unroll
        for (int j = 0; j < 8; j++) {
            int r = r0 + 16 * j;
            float4 v = *(const float4*)(A + r * PA + c4 * 4);
            __nv_bfloat162 h0 = __floats2bfloat162_rn(v.x, v.y);
            __nv_bfloat162 h1 = __floats2bfloat162_rn(v.z, v.w);
            uint2 u;
            u.x = *(unsigned*)&h0;
            u.y = *(unsigned*)&h1;
            *(uint2*)(Ab + r * PB + c4 * 4) = u;
        }
        // dense copy: lanes contiguous -> 1 wavefront per STG.32
        float* orow = outF + (size_t)rowBase * DD + ck * BK;
#pragma unroll
        for (int j = 0; j < 16; j++) {
            int r = warp + 8 * j;
            __stcs(orow + (size_t)r * DD + lane,      A[r * PA + lane]);
            __stcs(orow + (size_t)r * DD + 32 + lane, A[r * PA + 32 + lane]);
        }
    };

    const int matid = lane >> 3, mr = lane & 7;

    // prologue: 3 groups in flight; convert chunk 0
    prefetch(0);
    prefetch(1);
    prefetch(2);
    CP_WAIT(2);          // group 0 complete (this thread)
    __syncthreads();     // ... and all threads
    convert(0);

#pragma unroll 1
    for (int c = 0; c < NCHUNK; c++) {
        // need group c+1 complete before the barrier (for convert(c+1))
        if (c + 1 < NCHUNK) {
            if (c + 2 <= NCHUNK - 1) CP_WAIT(1);
            else                     CP_WAIT(0);
        }
        __syncthreads();
        if (c + 3 < NCHUNK) prefetch(c + 3);
        if (c + 1 < NCHUNK) convert(c + 1);

        // mma chunk c from Ab[c&1] (written last iteration, pre-barrier)
        const __nv_bfloat16* Ab = bufA(c & 1);
        const __nv_bfloat16* Bs = stB(c & (NSTAGE - 1));
#pragma unroll
        for (int ks = 0; ks < 4; ks++) {
            unsigned af[2][4], bf2[2][4];
#pragma unroll
            for (int mi = 0; mi < 2; mi++) {
                const __nv_bfloat16* p =
                    Ab + (wm * 32 + mi * 16 + (matid & 1) * 8 + mr) * PB +
                    ks * 16 + (matid >> 1) * 8;
                unsigned ad = (unsigned)__cvta_generic_to_shared(p);
                LDSM4(af[mi][0], af[mi][1], af[mi][2], af[mi][3], ad);
            }
#pragma unroll
            for (int gi = 0; gi < 2; gi++) {
                const __nv_bfloat16* p =
                    Bs + (wn * 32 + gi * 16 + (matid >> 1) * 8 + mr) * PB +
                    ks * 16 + (matid & 1) * 8;
                unsigned ad = (unsigned)__cvta_generic_to_shared(p);
                LDSM4(bf2[gi][0], bf2[gi][1], bf2[gi][2], bf2[gi][3], ad);
            }
#pragma unroll
            for (int mi = 0; mi < 2; mi++)
#pragma unroll
                for (int nt = 0; nt < 4; nt++)
                    MMA16816(acc[mi][nt], af[mi],
                             bf2[nt >> 1][(nt & 1) * 2],
                             bf2[nt >> 1][(nt & 1) * 2 + 1]);
        }
    }

    // epilogue: accums -> smem transpose -> g_mat[b][j]
    __syncthreads();
    float* sC = (float*)smem;  // [128][65]
    const int g = lane >> 2, t4 = lane & 3;
#pragma unroll
    for (int mi = 0; mi < 2; mi++)
#pragma unroll
        for (int nt = 0; nt < 4; nt++) {
            int ml = wm * 32 + mi * 16 + g;
            int nn = wn * 32 + nt * 8 + t4 * 2;
            sC[ml * 65 + nn]           = acc[mi][nt][0];
            sC[ml * 65 + nn + 1]       = acc[mi][nt][1];
            sC[(ml + 8) * 65 + nn]     = acc[mi][nt][2];
            sC[(ml + 8) * 65 + nn + 1] = acc[mi][nt][3];
        }
    __syncthreads();
#pragma unroll 1
    for (int i = 0; i < 32; i++) {
        int e = i * 256 + tid;
        int bb = e >> 7, j = e & 127;
        g_mat[bb * NB + rowBase + j] = sC[j * 65 + bb];
    }
}

// ---------------------------------------------------------------------------
// K2: blocks 0..255  -> per-(row, quarter) loss reduction; last of the 256
//                       combines quarters, writes mean loss, resets counter.
//     blocks 256..319 -> momentum update of bank row for batch b = bx - 256
//                       (independent of g_mat -> fully parallel with loss).
// Threshold max-25: exp(-25)~1.4e-11 -> identical to exact top-K lse.
// ---------------------------------------------------------------------------
__global__ __launch_bounds__(256) void post_kernel(
    const int* __restrict__ labels, const int* __restrict__ indexes,
    const float* __restrict__ feats, const float* __restrict__ fweak,
    float* __restrict__ out)
{
    __shared__ float sM[256], sP[256], sS[256];
    __shared__ int s_last;
    const int bx = blockIdx.x;
    const int tid = threadIdx.x;

    if (bx >= 256) {
        // ---- momentum update (last duplicate index wins) ----
        const int b = bx - 256;
        const int idx = indexes[b];
        for (int b2 = b + 1; b2 < BQ; b2++)
            if (indexes[b2] == idx) return;

        float w[8];
        float ssum = 0.f;
        const float* fr = feats + (size_t)idx * DD;
        const float* wr = fweak + (size_t)b * DD;
#pragma unroll
        for (int i = 0; i < 8; i++) {
            int k = i * 256 + tid;
            float v = fr[k] * 0.2f + wr[k] * 0.8f;
            w[i] = v;
            ssum += v * v;
        }
        sS[tid] = ssum;
        __syncthreads();
        for (int o = 128; o > 0; o >>= 1) {
            if (tid < o) sS[tid] += sS[tid + o];
            __syncthreads();
        }
        float inv = 1.0f / fmaxf(sqrtf(sS[0]), 1e-12f);
        float* orow = out + 1 + (size_t)idx * DD;
#pragma unroll
        for (int i = 0; i < 8; i++) orow[i * 256 + tid] = w[i] * inv;
        return;
    }

    // ---- loss quarter ----
    const int b = bx >> 2, q = bx & 3;
    const int blab = labels[indexes[b]];
    const float it = 1.0f / 0.07f;

    const float4* row4 = (const float4*)(g_mat + b * NB) + q * 1024;
    const int4*   lab4 = (const int4*)labels + q * 1024;

    float v[16];
    int   neg[16];
    float mneg = -INFINITY, pmin = INFINITY;
#pragma unroll
    for (int k = 0; k < 4; k++) {
        float4 v4 = row4[tid + k * 256];
        int4   l4 = lab4[tid + k * 256];
        v[k * 4 + 0] = v4.x * it; neg[k * 4 + 0] = (l4.x != blab);
        v[k * 4 + 1] = v4.y * it; neg[k * 4 + 1] = (l4.y != blab);
        v[k * 4 + 2] = v4.z * it; neg[k * 4 + 2] = (l4.z != blab);
        v[k * 4 + 3] = v4.w * it; neg[k * 4 + 3] = (l4.w != blab);
    }
#pragma unroll
    for (int k = 0; k < 16; k++) {
        if (neg[k]) mneg = fmaxf(mneg, v[k]);
        else        pmin = fminf(pmin, v[k]);
    }
    float tmax = mneg;
    sM[tid] = mneg; sP[tid] = pmin;
    __syncthreads();
    for (int o = 128; o > 0; o >>= 1) {
        if (tid < o) {
            sM[tid] = fmaxf(sM[tid], sM[tid + o]);
            sP[tid] = fminf(sP[tid], sP[tid + o]);
        }
        __syncthreads();
    }
    const float M = sM[0];
    const float thr = M - 25.0f;

    float s = 0.f;
    if (tmax > thr) {
#pragma unroll
        for (int k = 0; k < 16; k++)
            if (neg[k] && v[k] > thr) s += __expf(v[k] - M);
    }
    __syncthreads();
    sS[tid] = s;
    __syncthreads();
    for (int o = 128; o > 0; o >>= 1) {
        if (tid < o) sS[tid] += sS[tid + o];
        __syncthreads();
    }
    if (tid == 0) {
        g_qm[bx] = M;
        g_qs[bx] = sS[0];
        g_qp[bx] = sP[0];
        __threadfence();
        unsigned c = atomicAdd(&g_cnt, 1u);
        s_last = (c == 4 * BQ - 1);
    }
    __syncthreads();

    if (s_last) {
        float rl = 0.f;
        if (tid < BQ) {
            float m = -INFINITY, p = INFINITY;
#pragma unroll
            for (int qq = 0; qq < 4; qq++) {
                m = fmaxf(m, *((volatile float*)&g_qm[tid * 4 + qq]));
                p = fminf(p, *((volatile float*)&g_qp[tid * 4 + qq]));
            }
            float ss = 0.f;
#pragma unroll
            for (int qq = 0; qq < 4; qq++) {
                float mq = *((volatile float*)&g_qm[tid * 4 + qq]);
                if (mq > -INFINITY)
                    ss += *((volatile float*)&g_qs[tid * 4 + qq]) *
                          __expf(mq - m);
            }
            float nm = fmaxf(m, p);
            float ns = ss * __expf(m - nm) + __expf(p - nm);
            rl = nm + logf(ns) - p;  // lse - logit0
        }
        sS[tid] = (tid < BQ) ? rl : 0.f;
        __syncthreads();
        for (int o = 128; o > 0; o >>= 1) {
            if (tid < o) sS[tid] += sS[tid + o];
            __syncthreads();
        }
        if (tid == 0) {
            out[0] = sS[0] * (1.0f / 64.0f);
            g_cnt = 0;  // reset for next graph replay
        }
    }
}

// ---------------------------------------------------------------------------
extern "C" void kernel_launch(void* const* d_in, const int* in_sizes, int n_in,
                              void* d_out, int out_size)
{
    const float* fq      = (const float*)d_in[0];  // f        [64,2048]
    const float* fweak   = (const float*)d_in[1];  // f_weak   [64,2048]
    const int*   indexes = (const int*)d_in[2];    // [64]
    const float* feats   = (const float*)d_in[3];  // features [16384,2048]
    const int*   labels  = (const int*)d_in[4];    // [16384]
    float* out = (float*)d_out;                    // [0]=loss, [1:]=features

    cudaFuncSetAttribute(gemm_copy_kernel,
                         cudaFuncAttributeMaxDynamicSharedMemorySize,
                         SMEM_BYTES);

    prep_kernel<<<BQ * DD / (256 * 4), 256>>>(fq);
    gemm_copy_kernel<<<NB / BM, 256, SMEM_BYTES>>>(feats, out + 1);
    post_kernel<<<BQ * 4 + BQ, 256>>>(labels, indexes, feats, fweak, out);
}